// round 6
// baseline (speedup 1.0000x reference)
#include <cuda_runtime.h>
#include <cstdint>
#include <cstddef>

// Problem dims (fixed by the reference)
#define NB    32          // batch
#define TT    2048        // seq
#define MMI   64          // input dim m
#define PPO   64          // output dim p
#define NSTA  512         // state dim n
#define NROWS (NB * TT)   // 65536 flattened (b,t) rows
#define KB    32          // scan block length (time steps per block)
#define NBLK  (TT / KB)   // 64 blocks

// Scratch (device-global: no cudaMalloc allowed)
__device__ float g_Bu[NROWS * NSTA];
__device__ float g_x [NROWS * NSTA];

// ---------------------------------------------------------------------------
// K1: g_Bu[r][n] = sum_m u[r][m] * B[n][m]   (unchanged from R4)
// ---------------------------------------------------------------------------
__global__ void __launch_bounds__(256) k_bu(const float* __restrict__ u,
                                            const float* __restrict__ Bm) {
    __shared__ float us[128][33];
    __shared__ float bs[64][33];

    const int r0  = blockIdx.x * 128;
    const int n0  = blockIdx.y * 64;
    const int tid = threadIdx.x;
    const int tx  = tid & 15;
    const int ty  = tid >> 4;
    const int lr  = tid >> 3;
    const int lk  = (tid & 7) * 4;

    float acc[8][4];
#pragma unroll
    for (int i = 0; i < 8; i++)
#pragma unroll
        for (int j = 0; j < 4; j++) acc[i][j] = 0.0f;

#pragma unroll
    for (int c = 0; c < 2; c++) {
#pragma unroll
        for (int pass = 0; pass < 4; ++pass) {
            int row = lr + pass * 32;
            float4 v = *reinterpret_cast<const float4*>(
                u + (size_t)(r0 + row) * MMI + c * 32 + lk);
            us[row][lk + 0] = v.x; us[row][lk + 1] = v.y;
            us[row][lk + 2] = v.z; us[row][lk + 3] = v.w;
        }
#pragma unroll
        for (int pass = 0; pass < 2; ++pass) {
            int n = lr + pass * 32;
            float4 v = *reinterpret_cast<const float4*>(
                Bm + (size_t)(n0 + n) * MMI + c * 32 + lk);
            bs[n][lk + 0] = v.x; bs[n][lk + 1] = v.y;
            bs[n][lk + 2] = v.z; bs[n][lk + 3] = v.w;
        }
        __syncthreads();
#pragma unroll
        for (int k = 0; k < 32; k++) {
            float av[8], bv[4];
#pragma unroll
            for (int i = 0; i < 8; i++) av[i] = us[ty * 8 + i][k];
#pragma unroll
            for (int j = 0; j < 4; j++) bv[j] = bs[tx * 4 + j][k];
#pragma unroll
            for (int i = 0; i < 8; i++)
#pragma unroll
                for (int j = 0; j < 4; j++)
                    acc[i][j] = fmaf(av[i], bv[j], acc[i][j]);
        }
        __syncthreads();
    }

#pragma unroll
    for (int i = 0; i < 8; i++) {
        float4 v = make_float4(acc[i][0], acc[i][1], acc[i][2], acc[i][3]);
        *reinterpret_cast<float4*>(
            g_Bu + (size_t)(r0 + ty * 8 + i) * NSTA + n0 + tx * 4) = v;
    }
}

// ---------------------------------------------------------------------------
// K2: blocked companion scan. One CTA per batch, 512 threads, K=32 steps/block.
//
// Companion step: x_t[i] = x_{t-1}[i-1] + f[i]*z_{t-1} + bu_t[i],  f[i]=-a[511-i],
//                 z_t = x_t[511],  x_t[-1] := 0.
//
// Per 32-step block (start state X, z0 = X[511]):
//  * z-chain (warp 15 only): z_{t0+k} = base_k - sum_{m=1}^{k-1} a[k-1-m] z_{t0+m}
//      base_k = X[511-k] + sum_{j=1..k} bu_{t0+j}[511-k+j],  b_k = base_k - a[k-1] z0.
//    Unit-lower-tri Toeplitz solve -> z_k = sum_m g[k-m] b_m with precomputed
//    impulse response g (g0=1, g_q = -sum a[j-1] g_{q-j}). Two 32-tap dot loops.
//  * parallel phase: thread i traces origin o=i-32 ("diagonal" of the shift):
//      v <- v + f[o+k]*z_{k-1} + bu_k[o+k], written to g_x each step.
//    End of block: thread i's v IS the new X[i]. Threads 0..31 also trace the
//    32 short top diagonals (origins 480+i), balancing work to 32 iters/thread.
//  Bu tiles (64KB) double-buffered via cp.async. 2 barriers per block.
// ---------------------------------------------------------------------------
struct ScanSmem {
    float butile[2][KB * NSTA];  // 131072 B
    float xs[2][NSTA];           // block-start state, double buffered
    float fs[NSTA];              // f[i] = -a[511-i]
    float zarr[KB + 1];          // zarr[0]=z0, zarr[k]=z_{t0+k}
    float z0arr[2];              // z0 per block parity
    float as[KB];                // a[0..31]
    float gs[KB];                // impulse response g[0..31]
    float barr[KB];              // b_k staging
};

__device__ __forceinline__ unsigned su32(const void* p) {
    return (unsigned)__cvta_generic_to_shared(p);
}
__device__ __forceinline__ void cp16(void* smem_dst, const void* gsrc) {
    asm volatile("cp.async.cg.shared.global [%0], [%1], 16;"
                 :: "r"(su32(smem_dst)), "l"(gsrc));
}
__device__ __forceinline__ void cp_commit() { asm volatile("cp.async.commit_group;"); }
__device__ __forceinline__ void cp_wait0()  { asm volatile("cp.async.wait_group 0;"); }

__global__ void __launch_bounds__(512) k_scan_blk(const float* __restrict__ a) {
    extern __shared__ char raw[];
    ScanSmem* s = reinterpret_cast<ScanSmem*>(raw);
    const int b = blockIdx.x;
    const int i = threadIdx.x;

    s->fs[i] = -a[511 - i];
    s->xs[0][i] = 0.0f;
    if (i < KB) s->as[i] = a[i];
    if (i == 0) s->z0arr[0] = 0.0f;
    __syncthreads();
    if (i == 0) {
        // impulse response of the 32-tap IIR (once per CTA, serial, tiny)
        s->gs[0] = 1.0f;
        for (int k = 1; k < KB; k++) {
            float acc = 0.0f;
            for (int j = 1; j <= k; j++) acc += s->as[j - 1] * s->gs[k - j];
            s->gs[k] = -acc;
        }
    }

    const float* bu_g = g_Bu + (size_t)b * (TT * NSTA);
    float*       xo   = g_x  + (size_t)b * (TT * NSTA);

    // preload block 0 Bu tile
    {
        float* dst = s->butile[0];
#pragma unroll
        for (int r = 0; r < 8; r++) {
            int q = i + r * 512;                 // float4 index
            cp16(dst + q * 4, bu_g + q * 4);
        }
        cp_commit();
        cp_wait0();
    }
    __syncthreads();   // also publishes fs/gs/as/xs init

    for (int m = 0; m < NBLK; m++) {
        const int cur = m & 1;
        const float* bu  = s->butile[cur];
        const float* xsc = s->xs[cur];

        // prefetch next block's Bu tile into the other buffer
        if (m + 1 < NBLK) {
            const float* src = bu_g + (size_t)(m + 1) * KB * NSTA;
            float* dst = s->butile[cur ^ 1];
#pragma unroll
            for (int r = 0; r < 8; r++) {
                int q = i + r * 512;
                cp16(dst + q * 4, src + q * 4);
            }
            cp_commit();
        }

        // ---- z-chain: warp 15 only ----
        if (i >= 480) {
            const int l = i - 480;    // lane 0..31
            const int k = l + 1;      // 1..32
            float base = xsc[511 - k];
#pragma unroll
            for (int j = 1; j <= KB; j++)
                if (j <= k) base += bu[(j - 1) * NSTA + (510 - l + j)];
            float z0 = s->z0arr[cur];
            s->barr[l] = base - s->as[l] * z0;
            if (l == 0) s->zarr[0] = z0;
            __syncwarp();
            float z = 0.0f;
#pragma unroll
            for (int mm = 0; mm < KB; mm++)
                if (mm <= l) z += s->gs[l - mm] * s->barr[mm];
            s->zarr[k] = z;
        }
        __syncthreads();

        // ---- parallel diagonal update ----
        const int t0 = m * KB;
        float v  = (i >= KB) ? xsc[i - KB]  : 0.0f;  // origin o = i-32
        float v2 = (i <  KB) ? xsc[480 + i] : 0.0f;  // short origin 480+i
#pragma unroll
        for (int k = 1; k <= KB; k++) {
            float zk = s->zarr[k - 1];
            int p = i - KB + k;
            if (p == 0) {
                v = s->fs[0] * zk + bu[(k - 1) * NSTA];
                xo[(size_t)(t0 + k - 1) * NSTA] = v;
            } else if (p > 0) {
                v += s->fs[p] * zk + bu[(k - 1) * NSTA + p];
                xo[(size_t)(t0 + k - 1) * NSTA + p] = v;
            }
            if (i < KB) {
                int p2 = 480 + i + k;
                if (p2 < NSTA) {
                    v2 += s->fs[p2] * zk + bu[(k - 1) * NSTA + p2];
                    xo[(size_t)(t0 + k - 1) * NSTA + p2] = v2;
                }
            }
        }
        s->xs[cur ^ 1][i] = v;                 // thread i holds new X[i]
        if (i == 511) s->z0arr[cur ^ 1] = v;   // new z0
        cp_wait0();                            // next Bu tile landed
        __syncthreads();
    }
}

// ---------------------------------------------------------------------------
// K3: y[r][p] = sum_n C[p][n] x[r][n] + sum_m D[p][m] u[r][m]  (unchanged)
// ---------------------------------------------------------------------------
__global__ void __launch_bounds__(256) k_out(const float* __restrict__ u,
                                             const float* __restrict__ Cm,
                                             const float* __restrict__ Dm,
                                             float* __restrict__ y) {
    __shared__ float xs[128][33];
    __shared__ float cs[64][33];

    const int r0  = blockIdx.x * 128;
    const int tid = threadIdx.x;
    const int tx  = tid & 15;
    const int ty  = tid >> 4;
    const int lr  = tid >> 3;
    const int lk  = (tid & 7) * 4;

    float acc[8][4];
#pragma unroll
    for (int i = 0; i < 8; i++)
#pragma unroll
        for (int j = 0; j < 4; j++) acc[i][j] = 0.0f;

    for (int c = 0; c < 16; c++) {
#pragma unroll
        for (int pass = 0; pass < 4; ++pass) {
            int row = lr + pass * 32;
            float4 v = *reinterpret_cast<const float4*>(
                g_x + (size_t)(r0 + row) * NSTA + c * 32 + lk);
            xs[row][lk + 0] = v.x; xs[row][lk + 1] = v.y;
            xs[row][lk + 2] = v.z; xs[row][lk + 3] = v.w;
        }
#pragma unroll
        for (int pass = 0; pass < 2; ++pass) {
            int p = lr + pass * 32;
            float4 v = *reinterpret_cast<const float4*>(
                Cm + (size_t)p * NSTA + c * 32 + lk);
            cs[p][lk + 0] = v.x; cs[p][lk + 1] = v.y;
            cs[p][lk + 2] = v.z; cs[p][lk + 3] = v.w;
        }
        __syncthreads();
#pragma unroll
        for (int k = 0; k < 32; k++) {
            float av[8], bv[4];
#pragma unroll
            for (int i = 0; i < 8; i++) av[i] = xs[ty * 8 + i][k];
#pragma unroll
            for (int j = 0; j < 4; j++) bv[j] = cs[tx * 4 + j][k];
#pragma unroll
            for (int i = 0; i < 8; i++)
#pragma unroll
                for (int j = 0; j < 4; j++)
                    acc[i][j] = fmaf(av[i], bv[j], acc[i][j]);
        }
        __syncthreads();
    }

#pragma unroll
    for (int c = 0; c < 2; c++) {
#pragma unroll
        for (int pass = 0; pass < 4; ++pass) {
            int row = lr + pass * 32;
            float4 v = *reinterpret_cast<const float4*>(
                u + (size_t)(r0 + row) * MMI + c * 32 + lk);
            xs[row][lk + 0] = v.x; xs[row][lk + 1] = v.y;
            xs[row][lk + 2] = v.z; xs[row][lk + 3] = v.w;
        }
#pragma unroll
        for (int pass = 0; pass < 2; ++pass) {
            int p = lr + pass * 32;
            float4 v = *reinterpret_cast<const float4*>(
                Dm + (size_t)p * MMI + c * 32 + lk);
            cs[p][lk + 0] = v.x; cs[p][lk + 1] = v.y;
            cs[p][lk + 2] = v.z; cs[p][lk + 3] = v.w;
        }
        __syncthreads();
#pragma unroll
        for (int k = 0; k < 32; k++) {
            float av[8], bv[4];
#pragma unroll
            for (int i = 0; i < 8; i++) av[i] = xs[ty * 8 + i][k];
#pragma unroll
            for (int j = 0; j < 4; j++) bv[j] = cs[tx * 4 + j][k];
#pragma unroll
            for (int i = 0; i < 8; i++)
#pragma unroll
                for (int j = 0; j < 4; j++)
                    acc[i][j] = fmaf(av[i], bv[j], acc[i][j]);
        }
        __syncthreads();
    }

#pragma unroll
    for (int i = 0; i < 8; i++) {
        float4 v = make_float4(acc[i][0], acc[i][1], acc[i][2], acc[i][3]);
        *reinterpret_cast<float4*>(
            y + (size_t)(r0 + ty * 8 + i) * PPO + tx * 4) = v;
    }
}

// ---------------------------------------------------------------------------
extern "C" void kernel_launch(void* const* d_in, const int* in_sizes, int n_in,
                              void* d_out, int out_size) {
    const float* u  = (const float*)d_in[0];   // (32, 2048, 64)
    const float* a  = (const float*)d_in[1];   // (512,)
    const float* Bm = (const float*)d_in[2];   // (512, 64)
    const float* Cm = (const float*)d_in[3];   // (64, 512)
    const float* Dm = (const float*)d_in[4];   // (64, 64)
    float* y = (float*)d_out;                  // (32, 2048, 64)

    (void)in_sizes; (void)n_in; (void)out_size;

    k_bu<<<dim3(NROWS / 128, NSTA / 64), 256>>>(u, Bm);

    cudaFuncSetAttribute(k_scan_blk, cudaFuncAttributeMaxDynamicSharedMemorySize,
                         (int)sizeof(ScanSmem));
    k_scan_blk<<<NB, 512, sizeof(ScanSmem)>>>(a);

    k_out<<<NROWS / 128, 256>>>(u, Cm, Dm, y);
}

// round 9
// speedup vs baseline: 1.1173x; 1.1173x over previous
#include <cuda_runtime.h>
#include <cstdint>
#include <cstddef>

#define NB    32
#define TT    2048
#define MMI   64
#define PPO   64
#define NSTA  512
#define NROWS (NB * TT)
#define KB    32              // trace block (time steps)
#define CHUNK 512             // time chunk per k_x CTA
#define NCH   (TT / CHUNK)    // 4
#define ZK    128             // z-IIR block

__device__ float g_Bu[NROWS * NSTA];
__device__ float g_x [NROWS * NSTA];
__device__ float g_d [NB * TT];
__device__ float g_z [NB * (TT + 1)];

// ---------------------------------------------------------------------------
__global__ void k_zero_d() {
    int i = blockIdx.x * blockDim.x + threadIdx.x;
    reinterpret_cast<float4*>(g_d)[i] = make_float4(0.f, 0.f, 0.f, 0.f);
}

// ---------------------------------------------------------------------------
// K1: Bu = u @ B^T, fused with anti-diagonal partial sums for d.
// d_t = sum over tile entries (ti, n) with ti + 511 - n == t-1 (per batch).
// ---------------------------------------------------------------------------
__global__ void __launch_bounds__(256) k_bu(const float* __restrict__ u,
                                            const float* __restrict__ Bm) {
    __shared__ float us[128][33];
    __shared__ float bs[64][33];
    __shared__ float dsh[192];

    const int r0  = blockIdx.x * 128;
    const int n0  = blockIdx.y * 64;
    const int tid = threadIdx.x;
    const int tx  = tid & 15;
    const int ty  = tid >> 4;
    const int lr  = tid >> 3;
    const int lk  = (tid & 7) * 4;

    if (tid < 192) dsh[tid] = 0.f;

    float acc[8][4];
#pragma unroll
    for (int i = 0; i < 8; i++)
#pragma unroll
        for (int j = 0; j < 4; j++) acc[i][j] = 0.0f;

#pragma unroll
    for (int c = 0; c < 2; c++) {
#pragma unroll
        for (int pass = 0; pass < 4; ++pass) {
            int row = lr + pass * 32;
            float4 v = *reinterpret_cast<const float4*>(
                u + (size_t)(r0 + row) * MMI + c * 32 + lk);
            us[row][lk + 0] = v.x; us[row][lk + 1] = v.y;
            us[row][lk + 2] = v.z; us[row][lk + 3] = v.w;
        }
#pragma unroll
        for (int pass = 0; pass < 2; ++pass) {
            int n = lr + pass * 32;
            float4 v = *reinterpret_cast<const float4*>(
                Bm + (size_t)(n0 + n) * MMI + c * 32 + lk);
            bs[n][lk + 0] = v.x; bs[n][lk + 1] = v.y;
            bs[n][lk + 2] = v.z; bs[n][lk + 3] = v.w;
        }
        __syncthreads();
#pragma unroll
        for (int k = 0; k < 32; k++) {
            float av[8], bv[4];
#pragma unroll
            for (int i = 0; i < 8; i++) av[i] = us[ty * 8 + i][k];
#pragma unroll
            for (int j = 0; j < 4; j++) bv[j] = bs[tx * 4 + j][k];
#pragma unroll
            for (int i = 0; i < 8; i++)
#pragma unroll
                for (int j = 0; j < 4; j++)
                    acc[i][j] = fmaf(av[i], bv[j], acc[i][j]);
        }
        __syncthreads();
    }

#pragma unroll
    for (int i = 0; i < 8; i++) {
        float4 v = make_float4(acc[i][0], acc[i][1], acc[i][2], acc[i][3]);
        *reinterpret_cast<float4*>(
            g_Bu + (size_t)(r0 + ty * 8 + i) * NSTA + n0 + tx * 4) = v;
    }

    // ---- d partials: per-thread reduce the 11 diagonals i-j = const ----
    float dl[11];
#pragma unroll
    for (int q = 0; q < 11; q++) dl[q] = 0.f;
#pragma unroll
    for (int i = 0; i < 8; i++)
#pragma unroll
        for (int j = 0; j < 4; j++) dl[i - j + 3] += acc[i][j];
    const int obase = ty * 8 - tx * 4 + 60;  // slot = (row_off - col_off) + 63
#pragma unroll
    for (int q = 0; q < 11; q++) atomicAdd(&dsh[obase + q], dl[q]);
    __syncthreads();
    if (tid < 192) {
        int bb  = r0 >> 11;                       // batch
        int idx = (r0 & 2047) + 448 - n0 + tid;   // local time index t-1
        if (idx < TT) atomicAdd(&g_d[bb * TT + idx], dsh[tid]);
    }
}

// ---------------------------------------------------------------------------
// K2a: scalar 512-tap IIR per batch:  z_t = d_t - sum_{j=1..512} a[j-1] z_{t-j}
// Blocked (ZK=128) via Toeplitz-inverse impulse response g.
// ---------------------------------------------------------------------------
__global__ void __launch_bounds__(512) k_ziir(const float* __restrict__ a) {
    __shared__ float zb[2561];    // zb[512+s] = z_s, s = -511..2048
    __shared__ float as[512];
    __shared__ float gs[ZK];
    __shared__ float bsol[ZK];

    const int b   = blockIdx.x;
    const int tid = threadIdx.x;

    as[tid] = a[tid];
    for (int i = tid; i < 2561; i += 512) zb[i] = 0.f;
    __syncthreads();

    // impulse response g[0..127] (warp 0, chunked warp-sequential)
    if (tid < 32) {
        const int l = tid;
        for (int c = 0; c < ZK; c += 32) {
            const int q = c + l;
            float H = 0.f;
            for (int j = q - c + 1; j <= q; j++)   // g-index q-j in [0, c-1]
                H += as[j - 1] * gs[q - j];
            float inner = 0.f;
            for (int m = 0; m < 32; m++) {
                float v = -(H + inner);
                if (c == 0 && m == 0) v = 1.f;     // g[0] = 1
                float gval = __shfl_sync(0xffffffffu, v, m);
                if (l == m) gs[q] = gval;
                else if (l > m) inner += as[l - m - 1] * gval;
            }
            __syncwarp();
        }
    }
    __syncthreads();

    const float* dp = g_d + (size_t)b * TT;
    const int k4 = (tid >> 2) + 1;  // position in block: 1..128
    const int qq = tid & 3;

    for (int blk = 0; blk < TT / ZK; blk++) {
        const int T0 = blk * ZK;
        const int t  = T0 + k4;
        // history part (z indices <= T0, incl. zero-padded s<=0)
        float H = 0.f;
        for (int j = k4 + qq; j <= 512; j += 4)
            H += as[j - 1] * zb[512 + t - j];
        H += __shfl_xor_sync(0xffffffffu, H, 1);
        H += __shfl_xor_sync(0xffffffffu, H, 2);
        if (qq == 0) bsol[k4 - 1] = dp[t - 1] - H;
        __syncthreads();
        // z_block = G * b  (lower-tri Toeplitz, parallel)
        float zv = 0.f;
        for (int m = 1 + qq; m <= k4; m += 4)
            zv += gs[k4 - m] * bsol[m - 1];
        zv += __shfl_xor_sync(0xffffffffu, zv, 1);
        zv += __shfl_xor_sync(0xffffffffu, zv, 2);
        if (qq == 0) zb[512 + t] = zv;
        __syncthreads();
    }

    for (int t = tid; t <= TT; t += 512)
        g_z[(size_t)b * (TT + 1) + t] = zb[512 + t];
}

// ---------------------------------------------------------------------------
// K2b: parallel state materialization. Grid = 32 batches x 4 chunks of 512.
// With z known the recurrence is shift-only: each diagonal resets at i==0,
// so chunks c>0 run 512 warm-up steps (no stores) then 512 storing steps.
// ---------------------------------------------------------------------------
struct XSmem {
    float butile[2][KB * NSTA];  // 131072 B
    float xs[2][NSTA];
    float fs[NSTA];
    float zs[2][KB];
};

__device__ __forceinline__ unsigned su32(const void* p) {
    return (unsigned)__cvta_generic_to_shared(p);
}
__device__ __forceinline__ void cp16(void* smem_dst, const void* gsrc) {
    asm volatile("cp.async.cg.shared.global [%0], [%1], 16;"
                 :: "r"(su32(smem_dst)), "l"(gsrc));
}
__device__ __forceinline__ void cp_commit() { asm volatile("cp.async.commit_group;"); }
__device__ __forceinline__ void cp_wait0()  { asm volatile("cp.async.wait_group 0;"); }

__global__ void __launch_bounds__(512) k_x(const float* __restrict__ a) {
    extern __shared__ char raw[];
    XSmem* s = reinterpret_cast<XSmem*>(raw);
    const int b = blockIdx.x >> 2;
    const int c = blockIdx.x & 3;
    const int i = threadIdx.x;

    s->fs[i] = -a[511 - i];
    s->xs[0][i] = 0.f;

    const int base_t  = (c == 0) ? 0 : (c * CHUNK - CHUNK);
    const int nblk    = (c == 0) ? (CHUNK / KB) : (2 * CHUNK / KB);
    const int wstore0 = (c == 0) ? 0 : (CHUNK / KB);

    const float* bu_g = g_Bu + ((size_t)b * TT + base_t) * NSTA;
    const float* z_g  = g_z + (size_t)b * (TT + 1) + base_t;  // z_{t-1}, t = base_t+1+..
    float*       xo   = g_x + (size_t)b * TT * NSTA;

    {   // preload tile 0
        float* dst = s->butile[0];
#pragma unroll
        for (int r = 0; r < 8; r++) { int q = i + r * 512; cp16(dst + q * 4, bu_g + q * 4); }
        cp_commit(); cp_wait0();
    }
    if (i < KB) s->zs[0][i] = z_g[i];
    __syncthreads();

    for (int w = 0; w < nblk; w++) {
        const int cur = w & 1;
        const float* bu  = s->butile[cur];
        const float* xsc = s->xs[cur];
        const float* zsc = s->zs[cur];

        if (w + 1 < nblk) {
            const float* src = bu_g + (size_t)(w + 1) * KB * NSTA;
            float* dst = s->butile[cur ^ 1];
#pragma unroll
            for (int r = 0; r < 8; r++) { int q = i + r * 512; cp16(dst + q * 4, src + q * 4); }
            cp_commit();
            if (i < KB) s->zs[cur ^ 1][i] = z_g[(size_t)(w + 1) * KB + i];
        }

        const bool st = (w >= wstore0);
        const int  tb = base_t + w * KB;        // t = tb+1 .. tb+32
        float v  = (i >= KB) ? xsc[i - KB]  : 0.f;
        float v2 = (i <  KB) ? xsc[480 + i] : 0.f;

#pragma unroll
        for (int k = 1; k <= KB; k++) {
            const float zk = zsc[k - 1];        // z_{t-1}
            int p = i - KB + k;
            if (p == 0) {
                v = s->fs[0] * zk + bu[(k - 1) * NSTA];
                if (st) xo[(size_t)(tb + k - 1) * NSTA] = v;
            } else if (p > 0) {
                v += s->fs[p] * zk + bu[(k - 1) * NSTA + p];
                if (st) xo[(size_t)(tb + k - 1) * NSTA + p] = v;
            }
            if (i < KB) {
                int p2 = 480 + i + k;
                if (p2 < NSTA) {
                    v2 += s->fs[p2] * zk + bu[(k - 1) * NSTA + p2];
                    if (st) xo[(size_t)(tb + k - 1) * NSTA + p2] = v2;
                }
            }
        }
        s->xs[cur ^ 1][i] = v;
        cp_wait0();
        __syncthreads();
    }
}

// ---------------------------------------------------------------------------
// K3: y = x @ C^T + u @ D^T   (unchanged)
// ---------------------------------------------------------------------------
__global__ void __launch_bounds__(256) k_out(const float* __restrict__ u,
                                             const float* __restrict__ Cm,
                                             const float* __restrict__ Dm,
                                             float* __restrict__ y) {
    __shared__ float xs[128][33];
    __shared__ float cs[64][33];

    const int r0  = blockIdx.x * 128;
    const int tid = threadIdx.x;
    const int tx  = tid & 15;
    const int ty  = tid >> 4;
    const int lr  = tid >> 3;
    const int lk  = (tid & 7) * 4;

    float acc[8][4];
#pragma unroll
    for (int i = 0; i < 8; i++)
#pragma unroll
        for (int j = 0; j < 4; j++) acc[i][j] = 0.0f;

    for (int c = 0; c < 16; c++) {
#pragma unroll
        for (int pass = 0; pass < 4; ++pass) {
            int row = lr + pass * 32;
            float4 v = *reinterpret_cast<const float4*>(
                g_x + (size_t)(r0 + row) * NSTA + c * 32 + lk);
            xs[row][lk + 0] = v.x; xs[row][lk + 1] = v.y;
            xs[row][lk + 2] = v.z; xs[row][lk + 3] = v.w;
        }
#pragma unroll
        for (int pass = 0; pass < 2; ++pass) {
            int p = lr + pass * 32;
            float4 v = *reinterpret_cast<const float4*>(
                Cm + (size_t)p * NSTA + c * 32 + lk);
            cs[p][lk + 0] = v.x; cs[p][lk + 1] = v.y;
            cs[p][lk + 2] = v.z; cs[p][lk + 3] = v.w;
        }
        __syncthreads();
#pragma unroll
        for (int k = 0; k < 32; k++) {
            float av[8], bv[4];
#pragma unroll
            for (int i = 0; i < 8; i++) av[i] = xs[ty * 8 + i][k];
#pragma unroll
            for (int j = 0; j < 4; j++) bv[j] = cs[tx * 4 + j][k];
#pragma unroll
            for (int i = 0; i < 8; i++)
#pragma unroll
                for (int j = 0; j < 4; j++)
                    acc[i][j] = fmaf(av[i], bv[j], acc[i][j]);
        }
        __syncthreads();
    }

#pragma unroll
    for (int c = 0; c < 2; c++) {
#pragma unroll
        for (int pass = 0; pass < 4; ++pass) {
            int row = lr + pass * 32;
            float4 v = *reinterpret_cast<const float4*>(
                u + (size_t)(r0 + row) * MMI + c * 32 + lk);
            xs[row][lk + 0] = v.x; xs[row][lk + 1] = v.y;
            xs[row][lk + 2] = v.z; xs[row][lk + 3] = v.w;
        }
#pragma unroll
        for (int pass = 0; pass < 2; ++pass) {
            int p = lr + pass * 32;
            float4 v = *reinterpret_cast<const float4*>(
                Dm + (size_t)p * MMI + c * 32 + lk);
            cs[p][lk + 0] = v.x; cs[p][lk + 1] = v.y;
            cs[p][lk + 2] = v.z; cs[p][lk + 3] = v.w;
        }
        __syncthreads();
#pragma unroll
        for (int k = 0; k < 32; k++) {
            float av[8], bv[4];
#pragma unroll
            for (int i = 0; i < 8; i++) av[i] = xs[ty * 8 + i][k];
#pragma unroll
            for (int j = 0; j < 4; j++) bv[j] = cs[tx * 4 + j][k];
#pragma unroll
            for (int i = 0; i < 8; i++)
#pragma unroll
                for (int j = 0; j < 4; j++)
                    acc[i][j] = fmaf(av[i], bv[j], acc[i][j]);
        }
        __syncthreads();
    }

#pragma unroll
    for (int i = 0; i < 8; i++) {
        float4 v = make_float4(acc[i][0], acc[i][1], acc[i][2], acc[i][3]);
        *reinterpret_cast<float4*>(
            y + (size_t)(r0 + ty * 8 + i) * PPO + tx * 4) = v;
    }
}

// ---------------------------------------------------------------------------
extern "C" void kernel_launch(void* const* d_in, const int* in_sizes, int n_in,
                              void* d_out, int out_size) {
    const float* u  = (const float*)d_in[0];
    const float* a  = (const float*)d_in[1];
    const float* Bm = (const float*)d_in[2];
    const float* Cm = (const float*)d_in[3];
    const float* Dm = (const float*)d_in[4];
    float* y = (float*)d_out;
    (void)in_sizes; (void)n_in; (void)out_size;

    k_zero_d<<<(NB * TT / 4) / 256, 256>>>();
    k_bu<<<dim3(NROWS / 128, NSTA / 64), 256>>>(u, Bm);
    k_ziir<<<NB, 512>>>(a);

    cudaFuncSetAttribute(k_x, cudaFuncAttributeMaxDynamicSharedMemorySize,
                         (int)sizeof(XSmem));
    k_x<<<NB * NCH, 512, sizeof(XSmem)>>>(a);

    k_out<<<NROWS / 128, 256>>>(u, Cm, Dm, y);
}